// round 1
// baseline (speedup 1.0000x reference)
#include <cuda_runtime.h>
#include <cuda_bf16.h>
#include <cstdint>

// Problem constants
#define BATCH 64
#define TSTEPS 2048
#define DIN 128
#define HID 256
#define DOUT 128
#define G4H (4*HID)        // 1024

// Scan kernel config
#define NCTA 128           // persistent CTAs (<=148, all co-resident)
#define HC 2               // hidden units per CTA (256/128)
#define NC 8               // gate columns per CTA (4 gates * HC)
#define KTOT (HID+DIN)     // 384 unified K (h part then x part)
#define KC 96              // K per warp-chunk (4 chunks)
#define NTHREADS 256

// SMEM layout (floats):
//  sK   : KTOT*BATCH      = 24576   (staged [k][b], rows 0..255 = h, 256..383 = x_t)
//  sW   : KTOT*NC         = 3072    ([k][c], c = gate*HC + lj)
//  sPart: 4*BATCH*9       = 2304    (padded stride 9 -> conflict-free)
//  sC   : BATCH*HC        = 128     (cell state, CTA-private)
//  sBias: NC              = 8
#define SM_K     0
#define SM_W     (KTOT*BATCH)
#define SM_PART  (SM_W + KTOT*NC)
#define SM_C     (SM_PART + 4*BATCH*9)
#define SM_BIAS  (SM_C + BATCH*HC)
#define SM_FLOATS (SM_BIAS + NC)
#define SMEM_BYTES (SM_FLOATS*4)

// Global scratch (static: no allocations allowed)
__device__ __align__(16) float g_xT[(size_t)TSTEPS * DIN * BATCH]; // [t][d][b]
__device__ __align__(16) float g_h[2][HID * BATCH];                // [k][b] double buffer
__device__ unsigned g_ctr;

// ---------------------------------------------------------------------------
// init: zero h buffer 0 and barrier counter (runs every launch -> deterministic)
// ---------------------------------------------------------------------------
__global__ void init_kernel() {
    int i = blockIdx.x * blockDim.x + threadIdx.x;
    if (i == 0) g_ctr = 0u;
    if (i < HID * BATCH) g_h[0][i] = 0.0f;
}

// ---------------------------------------------------------------------------
// transpose x [b][t][d] -> g_xT [t][d][b]  (coalesced both sides via tile)
// ---------------------------------------------------------------------------
__global__ void transpose_x_kernel(const float* __restrict__ x) {
    __shared__ float tile[BATCH][DIN + 1];
    int t = blockIdx.x;
    for (int i = threadIdx.x; i < BATCH * DIN; i += blockDim.x) {
        int b = i >> 7;          // /128
        int d = i & 127;
        tile[b][d] = x[((size_t)b * TSTEPS + t) * DIN + d];
    }
    __syncthreads();
    float* dst = g_xT + (size_t)t * DIN * BATCH;
    for (int i = threadIdx.x; i < BATCH * DIN; i += blockDim.x) {
        int d = i >> 6;          // /64
        int b = i & 63;
        dst[i] = tile[b][d];     // dst index = d*64 + b
    }
}

// ---------------------------------------------------------------------------
// persistent LSTM scan
// ---------------------------------------------------------------------------
__global__ void __launch_bounds__(NTHREADS, 1)
lstm_scan_kernel(const float* __restrict__ W_x,
                 const float* __restrict__ W_h,
                 const float* __restrict__ bias) {
    extern __shared__ float smem[];
    float* sK    = smem + SM_K;
    float* sW    = smem + SM_W;
    float* sPart = smem + SM_PART;
    float* sC    = smem + SM_C;
    float* sBias = smem + SM_BIAS;

    const int tid = threadIdx.x;
    const int cta = blockIdx.x;
    const int j0  = cta * HC;    // first owned hidden unit

    // Stage weights once: sW[k*NC + c], c = gate*HC + lj -> global col gate*HID + j0 + lj
    for (int idx = tid; idx < KTOT * NC; idx += NTHREADS) {
        int k = idx / NC, c = idx % NC;
        int gate = c / HC, lj = c % HC;
        int gcol = gate * HID + j0 + lj;
        sW[idx] = (k < HID) ? W_h[(size_t)k * G4H + gcol]
                            : W_x[(size_t)(k - HID) * G4H + gcol];
    }
    if (tid < NC) {
        int gate = tid / HC, lj = tid % HC;
        sBias[tid] = bias[gate * HID + j0 + lj];
    }
    for (int idx = tid; idx < BATCH * HC; idx += NTHREADS) sC[idx] = 0.0f;
    __syncthreads();

    const int warp = tid >> 5;
    const int lane = tid & 31;
    const int kc   = warp & 3;               // k chunk 0..3
    const int k0   = kc * KC;
    const int b    = ((warp >> 2) << 5) + lane;  // batch 0..63

    for (int s = 0; s < TSTEPS; s++) {
        const int rbuf = s & 1;

        // ---- stage h (L2, bypass stale L1) and x_t into sK ----
        {
            const float4* h4 = reinterpret_cast<const float4*>(g_h[rbuf]);
            float4* k4 = reinterpret_cast<float4*>(sK);
            #pragma unroll
            for (int i = 0; i < (HID * BATCH / 4) / NTHREADS; i++) {  // 16
                int idx = tid + i * NTHREADS;
                k4[idx] = __ldcg(&h4[idx]);
            }
            const float4* x4 = reinterpret_cast<const float4*>(
                g_xT + (size_t)s * DIN * BATCH);
            float4* kx4 = reinterpret_cast<float4*>(sK + HID * BATCH);
            #pragma unroll
            for (int i = 0; i < (DIN * BATCH / 4) / NTHREADS; i++) {  // 8
                int idx = tid + i * NTHREADS;
                kx4[idx] = x4[idx];
            }
        }
        __syncthreads();

        // ---- load my K-chunk of row b into registers (conflict-free, lanes b consecutive)
        float hreg[KC];
        #pragma unroll
        for (int i = 0; i < KC; i++) hreg[i] = sK[(k0 + i) * BATCH + b];

        // ---- partial GEMM: 8 columns, packed f32x2 FMA, warp-uniform LDS.64 of W pairs
        unsigned long long acc2[4];
        #pragma unroll
        for (int cp = 0; cp < 4; cp++) acc2[cp] = 0ull;

        const unsigned long long* wbase =
            reinterpret_cast<const unsigned long long*>(sW + k0 * NC);
        #pragma unroll
        for (int k = 0; k < KC; k++) {
            float hv = hreg[k];
            unsigned long long h2;
            asm("mov.b64 %0, {%1, %1};" : "=l"(h2) : "f"(hv));
            #pragma unroll
            for (int cp = 0; cp < 4; cp++) {
                unsigned long long w2 = wbase[k * 4 + cp];  // broadcast LDS.64
                asm("fma.rn.f32x2 %0, %1, %2, %0;"
                    : "+l"(acc2[cp]) : "l"(h2), "l"(w2));
            }
        }

        // ---- write partials (stride-9 padding -> conflict-free STS)
        #pragma unroll
        for (int cp = 0; cp < 4; cp++) {
            float lo, hi;
            asm("mov.b64 {%0, %1}, %2;" : "=f"(lo), "=f"(hi) : "l"(acc2[cp]));
            sPart[(kc * BATCH + b) * 9 + 2 * cp]     = lo;
            sPart[(kc * BATCH + b) * 9 + 2 * cp + 1] = hi;
        }
        __syncthreads();

        // ---- reduce 4 partials, activations, cell/h update (threads 0..127)
        if (tid < BATCH * HC) {
            int bb = tid & (BATCH - 1);
            int lj = tid >> 6;
            float g4[4];
            #pragma unroll
            for (int gate = 0; gate < 4; gate++) {
                int c = gate * HC + lj;
                float v = sBias[c];
                #pragma unroll
                for (int q = 0; q < 4; q++) v += sPart[(q * BATCH + bb) * 9 + c];
                g4[gate] = v;
            }
            float ig = 1.0f / (1.0f + __expf(-g4[0]));
            float fg = 1.0f / (1.0f + __expf(-g4[1]));
            float gg = tanhf(g4[2]);
            float og = 1.0f / (1.0f + __expf(-g4[3]));
            float cold = sC[bb * HC + lj];
            float cnew = fg * cold + ig * gg;
            sC[bb * HC + lj] = cnew;
            float hnew = og * tanhf(cnew);
            g_h[rbuf ^ 1][(j0 + lj) * BATCH + bb] = hnew;   // coalesced 128B
        }

        // ---- grid barrier (monotonic counter, reset by init kernel each launch)
        __threadfence();
        __syncthreads();
        if (tid == 0) {
            atomicAdd(&g_ctr, 1u);
            unsigned target = (unsigned)NCTA * (unsigned)(s + 1);
            while (*(volatile unsigned*)&g_ctr < target) { }
            __threadfence();
        }
        __syncthreads();
    }
}

// ---------------------------------------------------------------------------
// final FC: out[b][d] = sum_k h_final[k][b] * fc_w[k][d] + fc_b[d]
// (after 2048 steps final h lives in g_h[0])
// ---------------------------------------------------------------------------
__global__ void fc_kernel(const float* __restrict__ fc_w,
                          const float* __restrict__ fc_b,
                          float* __restrict__ out) {
    int b = blockIdx.x;
    int d = threadIdx.x;
    const float* hf = g_h[0];
    float acc = fc_b[d];
    #pragma unroll 8
    for (int k = 0; k < HID; k++)
        acc += hf[k * BATCH + b] * fc_w[k * DOUT + d];
    out[b * DOUT + d] = acc;
}

// ---------------------------------------------------------------------------
extern "C" void kernel_launch(void* const* d_in, const int* in_sizes, int n_in,
                              void* d_out, int out_size) {
    const float* x    = (const float*)d_in[0];
    const float* W_x  = (const float*)d_in[1];
    const float* W_h  = (const float*)d_in[2];
    const float* bvec = (const float*)d_in[3];
    const float* fc_w = (const float*)d_in[4];
    const float* fc_b = (const float*)d_in[5];
    float* out = (float*)d_out;

    cudaFuncSetAttribute(lstm_scan_kernel,
                         cudaFuncAttributeMaxDynamicSharedMemorySize, SMEM_BYTES);

    init_kernel<<<(HID * BATCH + 255) / 256, 256>>>();
    transpose_x_kernel<<<TSTEPS, 256>>>(x);
    lstm_scan_kernel<<<NCTA, NTHREADS, SMEM_BYTES>>>(W_x, W_h, bvec);
    fc_kernel<<<BATCH, DOUT>>>(fc_w, fc_b, out);
}